// round 1
// baseline (speedup 1.0000x reference)
#include <cuda_runtime.h>

#define HID 768
#define NTOK 8
#define FSZ 32
#define BATCH 64
#define TSTRIDE 33   // 32 + 1 pad: conflict-free [h][y] tile

// scratch (allocation-free rule: device globals)
__device__ float g_t[BATCH * NTOK * HID];
__device__ float g_cwsum[NTOK];

// ---------------------------------------------------------------------------
// Kernel 1: t = LN2( Linear_over_tokens( LN1(token) ) )   + cwsum side output
// grid = BATCH+1 blocks, 256 threads
// ---------------------------------------------------------------------------
__global__ __launch_bounds__(256) void prep_kernel(
    const float* __restrict__ token,
    const float* __restrict__ ln1_w, const float* __restrict__ ln1_b,
    const float* __restrict__ lin_w, const float* __restrict__ lin_b,
    const float* __restrict__ ln2_w, const float* __restrict__ ln2_b,
    const float* __restrict__ conv_w)
{
    __shared__ float s[NTOK][HID];
    __shared__ float lw[NTOK * NTOK + NTOK];

    int b    = blockIdx.x;
    int tid  = threadIdx.x;
    int lane = tid & 31;
    int w    = tid >> 5;      // 8 warps

    if (b == BATCH) {
        // cwsum[n] = sum_h conv_w[n,h]; warp w -> row w
        float sum = 0.f;
        for (int h = lane; h < HID; h += 32) sum += conv_w[w * HID + h];
        #pragma unroll
        for (int o = 16; o; o >>= 1) sum += __shfl_xor_sync(0xffffffffu, sum, o);
        if (lane == 0) g_cwsum[w] = sum;
        return;
    }

    if (tid < NTOK * NTOK) lw[tid] = lin_w[tid];
    if (tid < NTOK)        lw[NTOK * NTOK + tid] = lin_b[tid];

    for (int i = tid; i < NTOK * HID; i += 256)
        s[0][i] = token[(size_t)b * NTOK * HID + i];
    __syncthreads();

    // LN1: warp w handles token row w
    {
        float sum = 0.f, sq = 0.f;
        for (int h = lane; h < HID; h += 32) { float v = s[w][h]; sum += v; sq += v * v; }
        #pragma unroll
        for (int o = 16; o; o >>= 1) {
            sum += __shfl_xor_sync(0xffffffffu, sum, o);
            sq  += __shfl_xor_sync(0xffffffffu, sq,  o);
        }
        float mu  = sum * (1.f / HID);
        float var = sq  * (1.f / HID) - mu * mu;
        float rs  = rsqrtf(var + 1e-5f);
        for (int h = lane; h < HID; h += 32)
            s[w][h] = (s[w][h] - mu) * rs * ln1_w[h] + ln1_b[h];
    }
    __syncthreads();

    // Linear over token dim: per column h independent (read col, write col)
    for (int h = tid; h < HID; h += 256) {
        float v[NTOK];
        #pragma unroll
        for (int n = 0; n < NTOK; n++) v[n] = s[n][h];
        float o[NTOK];
        #pragma unroll
        for (int m = 0; m < NTOK; m++) {
            float a = lw[NTOK * NTOK + m];
            #pragma unroll
            for (int n = 0; n < NTOK; n++) a += lw[m * NTOK + n] * v[n];
            o[m] = a;
        }
        #pragma unroll
        for (int m = 0; m < NTOK; m++) s[m][h] = o[m];
    }
    __syncthreads();

    // LN2 + store to g_t
    {
        float sum = 0.f, sq = 0.f;
        for (int h = lane; h < HID; h += 32) { float v = s[w][h]; sum += v; sq += v * v; }
        #pragma unroll
        for (int o = 16; o; o >>= 1) {
            sum += __shfl_xor_sync(0xffffffffu, sum, o);
            sq  += __shfl_xor_sync(0xffffffffu, sq,  o);
        }
        float mu  = sum * (1.f / HID);
        float var = sq  * (1.f / HID) - mu * mu;
        float rs  = rsqrtf(var + 1e-5f);
        for (int h = lane; h < HID; h += 32)
            g_t[((size_t)b * NTOK + w) * HID + h] = (s[w][h] - mu) * rs * ln2_w[h] + ln2_b[h];
    }
}

// ---------------------------------------------------------------------------
// Kernel 2: per (b,x) tile of 32 y-rows:
//   oric[h][y] = (ori - mu_h) * rstd_h            (LN over y, eps = FS = 32.0!)
//   P[n][y]    = sum_h conv_w[n,h] * oric[h][y]
//   mix[n][y]  = sigmoid(lno_w[y]*P + lno_b[y]*cwsum[n])
//   out[y][h]  = sum_n t[b,n,h] * mix[n][y]
// grid = 64*32 = 2048 blocks, 768 threads, ~172 KB dyn smem
// ---------------------------------------------------------------------------
#define NWARP 24
#define SMEM_FLOATS (HID * TSTRIDE + HID * 8 + NTOK * HID + NWARP * 256 + 256)

__global__ __launch_bounds__(768, 1) void main_kernel(
    const float* __restrict__ ori,
    const float* __restrict__ lno_w, const float* __restrict__ lno_b,
    const float* __restrict__ conv_w,
    float* __restrict__ out)
{
    extern __shared__ float sm[];
    float* oric = sm;                        // [HID][TSTRIDE]  centered*rstd tile
    float* cw   = oric + HID * TSTRIDE;      // [h][8] conv_w transposed
    float* ts   = cw + HID * 8;              // [n][HID] t tile
    float* part = ts + NTOK * HID;           // [24 warps][32 y][8 n]
    float* mixs = part + NWARP * 256;        // [n][32 y]

    int tid  = threadIdx.x;
    int lane = tid & 31;
    int w    = tid >> 5;
    int b    = blockIdx.x >> 5;
    int x    = blockIdx.x & 31;

    const float* obase = ori + ((size_t)(b * 1024 + x * FSZ)) * HID;

    // Load this thread's h-column (h = tid) into registers; also stage cw & t
    float xv[FSZ];
    #pragma unroll
    for (int y = 0; y < FSZ; y++) xv[y] = obase[(size_t)y * HID + tid];
    #pragma unroll
    for (int k = 0; k < NTOK; k++) {
        cw[tid * 8 + k]  = conv_w[k * HID + tid];
        ts[k * HID + tid] = g_t[((size_t)b * NTOK + k) * HID + tid];
    }

    // Per-h LayerNorm over y (biased var, eps = featmap_size = 32.0f)
    float sum = 0.f, sq = 0.f;
    #pragma unroll
    for (int y = 0; y < FSZ; y++) { sum += xv[y]; sq += xv[y] * xv[y]; }
    float mu  = sum * (1.f / FSZ);
    float var = sq  * (1.f / FSZ) - mu * mu;
    float rs  = rsqrtf(var + (float)FSZ);
    #pragma unroll
    for (int y = 0; y < FSZ; y++)
        oric[tid * TSTRIDE + y] = (xv[y] - mu) * rs;
    __syncthreads();

    // GEMM: warp w covers h in [w*32, w*32+32), lane = y; acc over 8 n
    {
        float acc[8];
        #pragma unroll
        for (int n = 0; n < 8; n++) acc[n] = 0.f;
        int hb = w * 32;
        #pragma unroll
        for (int i = 0; i < 32; i++) {
            int h = hb + i;
            float o = oric[h * TSTRIDE + lane];
            float4 c0 = *(const float4*)&cw[h * 8];
            float4 c1 = *(const float4*)&cw[h * 8 + 4];
            acc[0] += c0.x * o; acc[1] += c0.y * o; acc[2] += c0.z * o; acc[3] += c0.w * o;
            acc[4] += c1.x * o; acc[5] += c1.y * o; acc[6] += c1.z * o; acc[7] += c1.w * o;
        }
        float4* pp = (float4*)&part[w * 256 + lane * 8];
        pp[0] = make_float4(acc[0], acc[1], acc[2], acc[3]);
        pp[1] = make_float4(acc[4], acc[5], acc[6], acc[7]);
    }
    __syncthreads();

    // Reduce partials + sigmoid gate
    if (tid < 256) {
        int n = tid & 7, y = tid >> 3;
        float P = 0.f;
        #pragma unroll
        for (int ww = 0; ww < NWARP; ww++) P += part[ww * 256 + y * 8 + n];
        float v = lno_w[y] * P + lno_b[y] * g_cwsum[n];
        mixs[n * 32 + y] = 1.f / (1.f + expf(-v));
    }
    __syncthreads();

    // Output: out[y][h] = sum_n t[n][h] * mix[n][y]; float4 coalesced stores
    float* ob = out + ((size_t)(b * 1024 + x * FSZ)) * HID;
    #pragma unroll
    for (int k = 0; k < 8; k++) {
        int task = tid + k * 768;      // 0..6143 = 32 y * 192 float4
        int y  = task / 192;
        int h4 = (task - y * 192) * 4;
        float4 r = make_float4(0.f, 0.f, 0.f, 0.f);
        #pragma unroll
        for (int n = 0; n < 8; n++) {
            float4 t4 = *(const float4*)&ts[n * HID + h4];
            float  mn = mixs[n * 32 + y];
            r.x += t4.x * mn; r.y += t4.y * mn; r.z += t4.z * mn; r.w += t4.w * mn;
        }
        *(float4*)&ob[(size_t)y * HID + h4] = r;
    }
}

// ---------------------------------------------------------------------------
extern "C" void kernel_launch(void* const* d_in, const int* in_sizes, int n_in,
                              void* d_out, int out_size)
{
    const float* token = (const float*)d_in[0];
    const float* ori   = (const float*)d_in[1];
    const float* ln1_w = (const float*)d_in[2];
    const float* ln1_b = (const float*)d_in[3];
    const float* lin_w = (const float*)d_in[4];
    const float* lin_b = (const float*)d_in[5];
    const float* ln2_w = (const float*)d_in[6];
    const float* ln2_b = (const float*)d_in[7];
    const float* lno_w = (const float*)d_in[8];
    const float* lno_b = (const float*)d_in[9];
    const float* conv_w= (const float*)d_in[10];

    const int smem_bytes = SMEM_FLOATS * sizeof(float);
    cudaFuncSetAttribute(main_kernel, cudaFuncAttributeMaxDynamicSharedMemorySize, smem_bytes);

    prep_kernel<<<BATCH + 1, 256>>>(token, ln1_w, ln1_b, lin_w, lin_b,
                                    ln2_w, ln2_b, conv_w);
    main_kernel<<<BATCH * FSZ, 768, smem_bytes>>>(ori, lno_w, lno_b, conv_w,
                                                  (float*)d_out);
}